// round 9
// baseline (speedup 1.0000x reference)
#include <cuda_runtime.h>
#include <cuda_bf16.h>
#include <stdint.h>
#include <math.h>

// ============================================================================
// ConvNorm via mma.sync bf16 split-precision implicit conv, tap-shift SMEM.
// R8: B operand (hi/lo split activations) precomputed into a halo-padded
// channels-last global tensor by k_split; conv kernel loads A and B purely
// with cp.async (no per-chunk gather/convert on the critical path).
// ============================================================================

#define C_IN   256
#define C_OUT  256
#define HH     56
#define WW     56
#define BATCH  32
#define HWSZ   3136
#define KD     (C_IN * 9)

#define PITCH  48                 // smem bytes/row: 16*3 -> conflict-free ldmatrix
#define ABUF   (9 * 128 * PITCH)  // 55296
#define BHALF  (348 * PITCH)      // 16704 (6*58 pixel rows)
#define BBUF   (2 * BHALF)        // hi + lo
#define OFF_B  (2 * ABUF)
#define SMEMT  (OFF_B + 2 * BBUF) // 177408

#define PLANE  (58 * 58 * 16)     // elements per (b,chunk,part) plane = 53824
#define PLANEB (PLANE * 2)        // bytes = 107648

__device__ float g_maxt;
__device__ __nv_bfloat16 g_wA[16 * 2 * 9 * 128 * 16];   // [chunk][mb][tap][co][ci]
__device__ __nv_bfloat16 g_xs[(size_t)BATCH * 16 * 2 * PLANE];  // [b][chunk][part][hp][wp][ci]
__device__ float g_scale[C_OUT];
__device__ float g_bias[C_OUT];

// ---------------------------------------------------------------------------
__device__ __forceinline__ float xla_tanhf(float x) {
    const float kClamp = 7.90531110763549805f;
    float xc = fminf(fmaxf(x, -kClamp), kClamp);
    float x2 = __fmul_rn(xc, xc);
    float p;
    p = __fmaf_rn(x2, -2.76076847742355e-16f, 2.00018790482477e-13f);
    p = __fmaf_rn(x2, p, -8.60467152213735e-11f);
    p = __fmaf_rn(x2, p,  5.12229709037114e-08f);
    p = __fmaf_rn(x2, p,  1.48572235717979e-05f);
    p = __fmaf_rn(x2, p,  6.37261928875436e-04f);
    p = __fmaf_rn(x2, p,  4.89352455891786e-03f);
    p = __fmul_rn(xc, p);
    float q;
    q = __fmaf_rn(x2, 1.19825839466702e-06f, 1.18534705686654e-04f);
    q = __fmaf_rn(x2, q, 2.26843463243900e-03f);
    q = __fmaf_rn(x2, q, 4.89352518554385e-03f);
    float r = __fdiv_rn(p, q);
    return (fabsf(x) < 0.0004f) ? x : r;
}

__global__ void k_reset() { g_maxt = 0.0f; }

__global__ void k_maxabs(const float* __restrict__ w, int n) {
    float m = 0.0f;
    for (int i = blockIdx.x * blockDim.x + threadIdx.x; i < n;
         i += gridDim.x * blockDim.x)
        m = fmaxf(m, fabsf(xla_tanhf(w[i])));
    #pragma unroll
    for (int o = 16; o; o >>= 1)
        m = fmaxf(m, __shfl_xor_sync(0xFFFFFFFFu, m, o));
    __shared__ float s[32];
    if ((threadIdx.x & 31) == 0) s[threadIdx.x >> 5] = m;
    __syncthreads();
    if (threadIdx.x < 32) {
        m = (threadIdx.x < (blockDim.x >> 5)) ? s[threadIdx.x] : 0.0f;
        #pragma unroll
        for (int o = 16; o; o >>= 1)
            m = fmaxf(m, __shfl_xor_sync(0xFFFFFFFFu, m, o));
        if (threadIdx.x == 0)
            atomicMax((int*)&g_maxt, __float_as_int(m));
    }
}

__global__ void k_pack(const float* __restrict__ w) {
    int idx = blockIdx.x * blockDim.x + threadIdx.x;
    if (idx >= C_OUT * KD) return;
    int co = idx / KD;
    int k  = idx - co * KD;
    int ci = k / 9;
    int tap = k - ci * 9;
    float tv = xla_tanhf(w[idx]);
    tv = __fadd_rn(__fdiv_rn(tv, __fmul_rn(2.0f, g_maxt)), 0.5f);
    float r = rintf(__fmul_rn(tv, 15.0f));
    float m = __fmaf_rn(2.0f, r, -15.0f);
    int chunk = ci >> 4, cw = ci & 15;
    int mb = co >> 7, mr = co & 127;
    g_wA[(((chunk * 2 + mb) * 9 + tap) * 128 + mr) * 16 + cw] = __float2bfloat16(m);
}

__global__ void k_chan(const float* __restrict__ gamma, const float* __restrict__ beta,
                       const float* __restrict__ mean,  const float* __restrict__ var) {
    int c = threadIdx.x;
    float inv = __fdiv_rn(gamma[c], __fsqrt_rn(__fadd_rn(var[c], 1e-5f)));
    g_scale[c] = inv;
    g_bias[c]  = __fadd_rn(beta[c], -__fmul_rn(mean[c], inv));
}

// ---------------------------------------------------------------------------
// k_split: x fp32 -> halo-padded channels-last bf16 hi/lo planes.
// grid.x = b*16*58 + chunk*58 + hp; 128 threads; one output row per block.
// ---------------------------------------------------------------------------
__global__ void k_split(const float* __restrict__ x) {
    const int hp    = blockIdx.x % 58;
    const int chunk = (blockIdx.x / 58) % 16;
    const int b     = blockIdx.x / (58 * 16);
    const int tid   = threadIdx.x;
    __shared__ float s[56 * 16];

    if (hp >= 1 && hp <= 56) {
        const int h = hp - 1;
        const float* xr = x + ((size_t)(b * C_IN + chunk * 16) * HH + h) * WW;
        for (int i = tid; i < 16 * 56; i += 128) {
            int ci = i / 56, w = i - ci * 56;
            s[w * 16 + ci] = __ldg(xr + ci * HWSZ + w);
        }
    }
    __syncthreads();

    __nv_bfloat16* basep = g_xs + (size_t)(b * 16 + chunk) * 2 * PLANE;
    const int rowoff = hp * 58 * 16;
    for (int j = tid; j < 58 * 16; j += 128) {
        int wp = j >> 4, ci = j & 15;
        float v = 0.0f;
        if (hp >= 1 && hp <= 56 && wp >= 1 && wp <= 56)
            v = s[(wp - 1) * 16 + ci];
        __nv_bfloat16 hv = __float2bfloat16(v);
        float lf = __fsub_rn(v, __bfloat162float(hv));
        __nv_bfloat16 lv = __float2bfloat16(lf);
        basep[rowoff + j]         = hv;
        basep[PLANE + rowoff + j] = lv;
    }
}

// ---------------------------------------------------------------------------
__device__ __forceinline__ uint32_t smem_u32(const void* p) {
    uint32_t a;
    asm("{ .reg .u64 t; cvta.to.shared.u64 t, %1; cvt.u32.u64 %0, t; }"
        : "=r"(a) : "l"(p));
    return a;
}
__device__ __forceinline__ void cp16(uint32_t dst, const void* src) {
    asm volatile("cp.async.cg.shared.global [%0], [%1], 16;"
                 :: "r"(dst), "l"(src) : "memory");
}
__device__ __forceinline__ void ldsm4(uint32_t* r, uint32_t a) {
    asm volatile("ldmatrix.sync.aligned.m8n8.x4.shared.b16 {%0,%1,%2,%3}, [%4];"
                 : "=r"(r[0]), "=r"(r[1]), "=r"(r[2]), "=r"(r[3]) : "r"(a));
}
__device__ __forceinline__ void ldsm2(uint32_t* r, uint32_t a) {
    asm volatile("ldmatrix.sync.aligned.m8n8.x2.shared.b16 {%0,%1}, [%2];"
                 : "=r"(r[0]), "=r"(r[1]) : "r"(a));
}
__device__ __forceinline__ void mma16816(float* d, const uint32_t* a, const uint32_t* b) {
    asm volatile("mma.sync.aligned.m16n8k16.row.col.f32.bf16.bf16.f32 "
                 "{%0,%1,%2,%3}, {%4,%5,%6,%7}, {%8,%9}, {%0,%1,%2,%3};"
                 : "+f"(d[0]), "+f"(d[1]), "+f"(d[2]), "+f"(d[3])
                 : "r"(a[0]), "r"(a[1]), "r"(a[2]), "r"(a[3]),
                   "r"(b[0]), "r"(b[1]));
}

// ---------------------------------------------------------------------------
// grid(448, 2): x = b*14 + htile, y = mb. 256 threads, 8 warps = 2m x 4n.
// ---------------------------------------------------------------------------
__global__ __launch_bounds__(256, 1)
void k_conv(float* __restrict__ out, const float* __restrict__ alpha_p) {
    extern __shared__ __align__(16) char smem[];
    const uint32_t sAu = smem_u32(smem);
    const uint32_t sBu = sAu + OFF_B;

    const int tid = threadIdx.x;
    const int wid = tid >> 5, l = tid & 31;
    const int wm = wid & 1, wn = wid >> 1;
    const int b  = blockIdx.x / 14;
    const int h0 = (blockIdx.x % 14) * 4;
    const int mb = blockIdx.y;

    // --- precompute B copy slots: 1392 cp16 = 2 parts x 6 rows x 58 px x 2 ---
    const char* xsb = (const char*)g_xs + (size_t)b * 16 * 2 * PLANEB;
    uint32_t bDst[6], bSrc[6];
    #pragma unroll
    for (int j = 0; j < 6; j++) {
        int idx = tid + j * 256;
        if (idx < 1392) {
            int part = idx / 696;
            int rem  = idx - part * 696;
            int row  = rem / 116;
            int k    = rem - row * 116;
            int px   = k >> 1, hf = k & 1;
            bDst[j] = (uint32_t)(part * BHALF + (row * 58 + px) * PITCH + hf * 16);
            bSrc[j] = (uint32_t)(part * PLANEB + ((h0 + row) * 58 + px) * 32 + hf * 16);
        } else { bDst[j] = 0xFFFFFFFFu; bSrc[j] = 0; }
    }

    auto loadA = [&](int chunk, int buf) {
        const char* src = (const char*)g_wA + (size_t)(chunk * 2 + mb) * 36864;
        uint32_t db = sAu + buf * ABUF;
        #pragma unroll
        for (int j = 0; j < 9; j++) {
            int idx = tid + j * 256;
            cp16(db + (idx >> 1) * PITCH + (idx & 1) * 16, src + idx * 16);
        }
    };
    auto loadB = [&](int chunk, int buf) {
        const char* src = xsb + (size_t)chunk * 2 * PLANEB;
        uint32_t db = sBu + buf * BBUF;
        #pragma unroll
        for (int j = 0; j < 6; j++)
            if (bDst[j] != 0xFFFFFFFFu)
                cp16(db + bDst[j], src + bSrc[j]);
    };

    float acc[4][7][4];
    #pragma unroll
    for (int a = 0; a < 4; a++)
        #pragma unroll
        for (int n = 0; n < 7; n++)
            #pragma unroll
            for (int q = 0; q < 4; q++) acc[a][n][q] = 0.0f;

    const uint32_t a_lrow  = (uint32_t)(l & 15) * PITCH + (l >> 4) * 16;
    const int      b_lrow4 = (l & 7) + ((l >= 16) ? 8 : 0);
    const uint32_t b_lbyte = ((l >> 3) & 1) * 16;

    // ---- prologue: stages 0 and 1 in flight ----
    loadA(0, 0); loadB(0, 0);
    asm volatile("cp.async.commit_group;" ::: "memory");
    loadA(1, 1); loadB(1, 1);
    asm volatile("cp.async.commit_group;" ::: "memory");

    #pragma unroll 1
    for (int chunk = 0; chunk < 16; chunk++) {
        const int cur = chunk & 1;
        asm volatile("cp.async.wait_group 1;" ::: "memory");
        __syncthreads();

        const uint32_t ab = sAu + cur * ABUF;
        const uint32_t bh = sBu + cur * BBUF;
        #pragma unroll
        for (int tap = 0; tap < 9; tap++) {
            const int kh = tap / 3, kw = tap - kh * 3;
            uint32_t aT[4][4];
            #pragma unroll
            for (int mt = 0; mt < 4; mt++)
                ldsm4(aT[mt], ab + (uint32_t)(tap * 128 + wm * 64 + mt * 16) * PITCH + a_lrow);
            const int rbase = (wn + kh) * 58 + kw;
            #pragma unroll
            for (int part = 0; part < 2; part++) {
                const uint32_t breg = bh + part * BHALF;
                uint32_t bT[7][2];
                #pragma unroll
                for (int ntp = 0; ntp < 3; ntp++) {
                    uint32_t t4[4];
                    ldsm4(t4, breg + (uint32_t)(rbase + ntp * 16 + b_lrow4) * PITCH + b_lbyte);
                    bT[2 * ntp][0] = t4[0]; bT[2 * ntp][1] = t4[1];
                    bT[2 * ntp + 1][0] = t4[2]; bT[2 * ntp + 1][1] = t4[3];
                }
                ldsm2(bT[6], breg + (uint32_t)(rbase + 48 + (l & 7)) * PITCH + b_lbyte);
                #pragma unroll
                for (int mt = 0; mt < 4; mt++)
                    #pragma unroll
                    for (int nt = 0; nt < 7; nt++)
                        mma16816(acc[mt][nt], aT[mt], bT[nt]);
            }
        }

        __syncthreads();   // all warps done reading buffer `cur`
        if (chunk + 2 < 16) {
            loadA(chunk + 2, cur);
            loadB(chunk + 2, cur);
            asm volatile("cp.async.commit_group;" ::: "memory");
        }
    }

    // ---- epilogue: BN fold + PACT quant ----
    const float av  = alpha_p[0];
    const float aon = __fdiv_rn(av, 15.0f);
    #pragma unroll
    for (int mt = 0; mt < 4; mt++) {
        #pragma unroll
        for (int sub = 0; sub < 2; sub++) {
            int co = mb * 128 + wm * 64 + mt * 16 + (l >> 2) + sub * 8;
            float sc15 = __fdiv_rn(g_scale[co], 15.0f);
            float bi   = g_bias[co];
            float* ob = out + (size_t)(b * C_OUT + co) * HWSZ + (h0 + wn) * 56;
            #pragma unroll
            for (int nt = 0; nt < 7; nt++) {
                float y0 = __fmaf_rn(acc[mt][nt][sub * 2 + 0], sc15, bi);
                float y1 = __fmaf_rn(acc[mt][nt][sub * 2 + 1], sc15, bi);
                y0 = fminf(fmaxf(y0, 0.0f), av);
                y1 = fminf(fmaxf(y1, 0.0f), av);
                float q0 = rintf(__fdiv_rn(__fmul_rn(y0, 15.0f), av));
                float q1 = rintf(__fdiv_rn(__fmul_rn(y1, 15.0f), av));
                *(float2*)(ob + nt * 8 + 2 * (l & 3)) =
                    make_float2(__fmul_rn(q0, aon), __fmul_rn(q1, aon));
            }
        }
    }
}

// ---------------------------------------------------------------------------
extern "C" void kernel_launch(void* const* d_in, const int* in_sizes, int n_in,
                              void* d_out, int out_size) {
    const float* x      = (const float*)d_in[0];
    const float* weight = (const float*)d_in[1];
    const float* gamma  = (const float*)d_in[2];
    const float* beta   = (const float*)d_in[3];
    const float* rmean  = (const float*)d_in[4];
    const float* rvar   = (const float*)d_in[5];
    const float* alpha  = (const float*)d_in[6];
    float* out = (float*)d_out;

    const int WELEMS = C_OUT * KD;

    cudaFuncSetAttribute(k_conv, cudaFuncAttributeMaxDynamicSharedMemorySize, SMEMT);

    k_reset<<<1, 1>>>();
    k_maxabs<<<256, 256>>>(weight, WELEMS);
    k_pack<<<(WELEMS + 255) / 256, 256>>>(weight);
    k_chan<<<1, C_OUT>>>(gamma, beta, rmean, rvar);
    k_split<<<BATCH * 16 * 58, 128>>>(x);

    dim3 grid(BATCH * 14, 2);
    k_conv<<<grid, 256, SMEMT>>>(out, alpha);
    (void)in_sizes; (void)n_in; (void)out_size;
}

// round 10
// speedup vs baseline: 1.3719x; 1.3719x over previous
#include <cuda_runtime.h>
#include <cuda_bf16.h>
#include <stdint.h>
#include <math.h>

// ============================================================================
// ConvNorm via mma.sync bf16 split-precision implicit conv, tap-shift SMEM.
// R10: M split over 4 CTA blocks (64 co), 32B-row XOR-swizzled SMEM ->
// 81.4KB/CTA -> 2 CTAs/SM; B operand precomputed (k_split) and loaded with
// cp.async. Warp layout 2m x 4n; acc[2][7][4].
// ============================================================================

#define C_IN   256
#define C_OUT  256
#define HH     56
#define WW     56
#define BATCH  32
#define HWSZ   3136
#define KD     (C_IN * 9)

#define AROWS  (9 * 64)            // rows per A chunk tile
#define ABUF   (AROWS * 32)        // 18432 bytes
#define BHALF  (348 * 32)          // 11136 (6*58 pixel rows)
#define BBUF   (2 * BHALF)         // hi + lo
#define OFF_B  (2 * ABUF)          // 36864
#define SMEMT  (OFF_B + 2 * BBUF)  // 81408

#define PLANE  (58 * 58 * 16)      // elements per (b,chunk,part) plane
#define PLANEB (PLANE * 2)

__device__ float g_maxt;
__device__ __nv_bfloat16 g_wA[16 * 4 * 9 * 64 * 16];   // [chunk][mbq][tap][co][ci]
__device__ __nv_bfloat16 g_xs[(size_t)BATCH * 16 * 2 * PLANE];
__device__ float g_scale[C_OUT];
__device__ float g_bias[C_OUT];

// swizzled 16B-slot offset for (row, half)
__device__ __forceinline__ uint32_t swz(uint32_t r, uint32_t h) {
    return r * 32 + ((h ^ ((r >> 2) & 1)) << 4);
}

// ---------------------------------------------------------------------------
__device__ __forceinline__ float xla_tanhf(float x) {
    const float kClamp = 7.90531110763549805f;
    float xc = fminf(fmaxf(x, -kClamp), kClamp);
    float x2 = __fmul_rn(xc, xc);
    float p;
    p = __fmaf_rn(x2, -2.76076847742355e-16f, 2.00018790482477e-13f);
    p = __fmaf_rn(x2, p, -8.60467152213735e-11f);
    p = __fmaf_rn(x2, p,  5.12229709037114e-08f);
    p = __fmaf_rn(x2, p,  1.48572235717979e-05f);
    p = __fmaf_rn(x2, p,  6.37261928875436e-04f);
    p = __fmaf_rn(x2, p,  4.89352455891786e-03f);
    p = __fmul_rn(xc, p);
    float q;
    q = __fmaf_rn(x2, 1.19825839466702e-06f, 1.18534705686654e-04f);
    q = __fmaf_rn(x2, q, 2.26843463243900e-03f);
    q = __fmaf_rn(x2, q, 4.89352518554385e-03f);
    float r = __fdiv_rn(p, q);
    return (fabsf(x) < 0.0004f) ? x : r;
}

__global__ void k_reset() { g_maxt = 0.0f; }

__global__ void k_maxabs(const float* __restrict__ w, int n) {
    float m = 0.0f;
    for (int i = blockIdx.x * blockDim.x + threadIdx.x; i < n;
         i += gridDim.x * blockDim.x)
        m = fmaxf(m, fabsf(xla_tanhf(w[i])));
    #pragma unroll
    for (int o = 16; o; o >>= 1)
        m = fmaxf(m, __shfl_xor_sync(0xFFFFFFFFu, m, o));
    __shared__ float s[32];
    if ((threadIdx.x & 31) == 0) s[threadIdx.x >> 5] = m;
    __syncthreads();
    if (threadIdx.x < 32) {
        m = (threadIdx.x < (blockDim.x >> 5)) ? s[threadIdx.x] : 0.0f;
        #pragma unroll
        for (int o = 16; o; o >>= 1)
            m = fmaxf(m, __shfl_xor_sync(0xFFFFFFFFu, m, o));
        if (threadIdx.x == 0)
            atomicMax((int*)&g_maxt, __float_as_int(m));
    }
}

__global__ void k_pack(const float* __restrict__ w) {
    int idx = blockIdx.x * blockDim.x + threadIdx.x;
    if (idx >= C_OUT * KD) return;
    int co = idx / KD;
    int k  = idx - co * KD;
    int ci = k / 9;
    int tap = k - ci * 9;
    float tv = xla_tanhf(w[idx]);
    tv = __fadd_rn(__fdiv_rn(tv, __fmul_rn(2.0f, g_maxt)), 0.5f);
    float r = rintf(__fmul_rn(tv, 15.0f));
    float m = __fmaf_rn(2.0f, r, -15.0f);
    int chunk = ci >> 4, cw = ci & 15;
    int mbq = co >> 6, mr = co & 63;
    g_wA[(((chunk * 4 + mbq) * 9 + tap) * 64 + mr) * 16 + cw] = __float2bfloat16(m);
}

__global__ void k_chan(const float* __restrict__ gamma, const float* __restrict__ beta,
                       const float* __restrict__ mean,  const float* __restrict__ var) {
    int c = threadIdx.x;
    float inv = __fdiv_rn(gamma[c], __fsqrt_rn(__fadd_rn(var[c], 1e-5f)));
    g_scale[c] = inv;
    g_bias[c]  = __fadd_rn(beta[c], -__fmul_rn(mean[c], inv));
}

// ---------------------------------------------------------------------------
// k_split: x fp32 -> halo-padded channels-last bf16 hi/lo planes.
// ---------------------------------------------------------------------------
__global__ void k_split(const float* __restrict__ x) {
    const int hp    = blockIdx.x % 58;
    const int chunk = (blockIdx.x / 58) % 16;
    const int b     = blockIdx.x / (58 * 16);
    const int tid   = threadIdx.x;
    __shared__ float s[56 * 16];

    if (hp >= 1 && hp <= 56) {
        const int h = hp - 1;
        const float* xr = x + ((size_t)(b * C_IN + chunk * 16) * HH + h) * WW;
        for (int i = tid; i < 16 * 56; i += 128) {
            int ci = i / 56, w = i - ci * 56;
            s[w * 16 + ci] = __ldg(xr + ci * HWSZ + w);
        }
    }
    __syncthreads();

    __nv_bfloat16* basep = g_xs + (size_t)(b * 16 + chunk) * 2 * PLANE;
    const int rowoff = hp * 58 * 16;
    for (int j = tid; j < 58 * 16; j += 128) {
        int wp = j >> 4, ci = j & 15;
        float v = 0.0f;
        if (hp >= 1 && hp <= 56 && wp >= 1 && wp <= 56)
            v = s[(wp - 1) * 16 + ci];
        __nv_bfloat16 hv = __float2bfloat16(v);
        float lf = __fsub_rn(v, __bfloat162float(hv));
        __nv_bfloat16 lv = __float2bfloat16(lf);
        basep[rowoff + j]         = hv;
        basep[PLANE + rowoff + j] = lv;
    }
}

// ---------------------------------------------------------------------------
__device__ __forceinline__ uint32_t smem_u32(const void* p) {
    uint32_t a;
    asm("{ .reg .u64 t; cvta.to.shared.u64 t, %1; cvt.u32.u64 %0, t; }"
        : "=r"(a) : "l"(p));
    return a;
}
__device__ __forceinline__ void cp16(uint32_t dst, const void* src) {
    asm volatile("cp.async.cg.shared.global [%0], [%1], 16;"
                 :: "r"(dst), "l"(src) : "memory");
}
__device__ __forceinline__ void ldsm4(uint32_t* r, uint32_t a) {
    asm volatile("ldmatrix.sync.aligned.m8n8.x4.shared.b16 {%0,%1,%2,%3}, [%4];"
                 : "=r"(r[0]), "=r"(r[1]), "=r"(r[2]), "=r"(r[3]) : "r"(a));
}
__device__ __forceinline__ void ldsm2(uint32_t* r, uint32_t a) {
    asm volatile("ldmatrix.sync.aligned.m8n8.x2.shared.b16 {%0,%1}, [%2];"
                 : "=r"(r[0]), "=r"(r[1]) : "r"(a));
}
__device__ __forceinline__ void mma16816(float* d, const uint32_t* a, const uint32_t* b) {
    asm volatile("mma.sync.aligned.m16n8k16.row.col.f32.bf16.bf16.f32 "
                 "{%0,%1,%2,%3}, {%4,%5,%6,%7}, {%8,%9}, {%0,%1,%2,%3};"
                 : "+f"(d[0]), "+f"(d[1]), "+f"(d[2]), "+f"(d[3])
                 : "r"(a[0]), "r"(a[1]), "r"(a[2]), "r"(a[3]),
                   "r"(b[0]), "r"(b[1]));
}

// ---------------------------------------------------------------------------
// grid(448, 4): x = b*14 + htile, y = mbq (64-co block). 256 threads,
// 8 warps = 2m(32 co) x 4n(one output row of 56). 2 CTAs/SM.
// ---------------------------------------------------------------------------
__global__ __launch_bounds__(256, 2)
void k_conv(float* __restrict__ out, const float* __restrict__ alpha_p) {
    extern __shared__ __align__(16) char smem[];
    const uint32_t sAu = smem_u32(smem);
    const uint32_t sBu = sAu + OFF_B;

    const int tid = threadIdx.x;
    const int wid = tid >> 5, l = tid & 31;
    const int wm = wid & 1, wn = wid >> 1;
    const int b  = blockIdx.x / 14;
    const int h0 = (blockIdx.x % 14) * 4;
    const int mbq = blockIdx.y;

    // --- B copy slots: 1392 cp16 = 2 parts x 348 rows x 2 halves ---
    const char* xsb = (const char*)g_xs + (size_t)b * 16 * 2 * PLANEB;
    uint32_t bDst[6], bSrc[6];
    #pragma unroll
    for (int j = 0; j < 6; j++) {
        int idx = tid + j * 256;
        if (idx < 1392) {
            int part = idx / 696;
            int rem  = idx - part * 696;
            int row  = rem / 116;              // halo row 0..5
            int k    = rem - row * 116;
            int px   = k >> 1, hf = k & 1;
            uint32_t r = (uint32_t)(row * 58 + px);
            bDst[j] = (uint32_t)(part * BHALF) + swz(r, hf);
            bSrc[j] = (uint32_t)(part * PLANEB + ((h0 + row) * 58 + px) * 32 + hf * 16);
        } else { bDst[j] = 0xFFFFFFFFu; bSrc[j] = 0; }
    }

    auto loadA = [&](int chunk, int buf) {
        const char* src = (const char*)g_wA + (size_t)(chunk * 4 + mbq) * ABUF;
        uint32_t db = sAu + buf * ABUF;
        #pragma unroll
        for (int j = 0; j < 5; j++) {
            int idx = tid + j * 256;           // 1152 16B units
            if (idx < 1152)
                cp16(db + swz((uint32_t)(idx >> 1), (uint32_t)(idx & 1)), src + idx * 16);
        }
    };
    auto loadB = [&](int chunk, int buf) {
        const char* src = xsb + (size_t)chunk * 2 * PLANEB;
        uint32_t db = sBu + buf * BBUF;
        #pragma unroll
        for (int j = 0; j < 6; j++)
            if (bDst[j] != 0xFFFFFFFFu)
                cp16(db + bDst[j], src + bSrc[j]);
    };

    float acc[2][7][4];
    #pragma unroll
    for (int a = 0; a < 2; a++)
        #pragma unroll
        for (int n = 0; n < 7; n++)
            #pragma unroll
            for (int q = 0; q < 4; q++) acc[a][n][q] = 0.0f;

    const uint32_t a_lr = (uint32_t)(l & 15);
    const uint32_t a_lh = (uint32_t)(l >> 4);
    const uint32_t b_lr4 = (uint32_t)((l & 7) + ((l >= 16) ? 8 : 0));
    const uint32_t b_lh  = (uint32_t)((l >> 3) & 1);

    // ---- prologue ----
    loadA(0, 0); loadB(0, 0);
    asm volatile("cp.async.commit_group;" ::: "memory");
    loadA(1, 1); loadB(1, 1);
    asm volatile("cp.async.commit_group;" ::: "memory");

    #pragma unroll 1
    for (int chunk = 0; chunk < 16; chunk++) {
        const int cur = chunk & 1;
        asm volatile("cp.async.wait_group 1;" ::: "memory");
        __syncthreads();

        const uint32_t ab = sAu + cur * ABUF;
        const uint32_t bh = sBu + cur * BBUF;
        #pragma unroll
        for (int tap = 0; tap < 9; tap++) {
            const int kh = tap / 3, kw = tap - kh * 3;
            // A fragments: 2 m-frags of 16 co
            uint32_t aT[2][4];
            #pragma unroll
            for (int mt = 0; mt < 2; mt++) {
                uint32_t r = (uint32_t)(tap * 64 + wm * 32 + mt * 16) + a_lr;
                ldsm4(aT[mt], ab + swz(r, a_lh));
            }
            const uint32_t rbase = (uint32_t)((wn + kh) * 58 + kw);
            // prefetch both parts' B fragments before the MMA block
            uint32_t bT[2][7][2];
            #pragma unroll
            for (int part = 0; part < 2; part++) {
                const uint32_t breg = bh + part * BHALF;
                #pragma unroll
                for (int ntp = 0; ntp < 3; ntp++) {
                    uint32_t t4[4];
                    uint32_t r = rbase + (uint32_t)(ntp * 16) + b_lr4;
                    ldsm4(t4, breg + swz(r, b_lh));
                    bT[part][2 * ntp][0] = t4[0]; bT[part][2 * ntp][1] = t4[1];
                    bT[part][2 * ntp + 1][0] = t4[2]; bT[part][2 * ntp + 1][1] = t4[3];
                }
                uint32_t r2 = rbase + 48u + (uint32_t)(l & 7);
                ldsm2(bT[part][6], breg + swz(r2, b_lh));
            }
            #pragma unroll
            for (int part = 0; part < 2; part++)
                #pragma unroll
                for (int mt = 0; mt < 2; mt++)
                    #pragma unroll
                    for (int nt = 0; nt < 7; nt++)
                        mma16816(acc[mt][nt], aT[mt], bT[part][nt]);
        }

        __syncthreads();
        if (chunk + 2 < 16) {
            loadA(chunk + 2, cur);
            loadB(chunk + 2, cur);
            asm volatile("cp.async.commit_group;" ::: "memory");
        }
    }

    // ---- epilogue: BN fold + PACT quant ----
    const float av  = alpha_p[0];
    const float aon = __fdiv_rn(av, 15.0f);
    #pragma unroll
    for (int mt = 0; mt < 2; mt++) {
        #pragma unroll
        for (int sub = 0; sub < 2; sub++) {
            int co = mbq * 64 + wm * 32 + mt * 16 + (l >> 2) + sub * 8;
            float sc15 = __fdiv_rn(g_scale[co], 15.0f);
            float bi   = g_bias[co];
            float* ob = out + (size_t)(b * C_OUT + co) * HWSZ + (h0 + wn) * 56;
            #pragma unroll
            for (int nt = 0; nt < 7; nt++) {
                float y0 = __fmaf_rn(acc[mt][nt][sub * 2 + 0], sc15, bi);
                float y1 = __fmaf_rn(acc[mt][nt][sub * 2 + 1], sc15, bi);
                y0 = fminf(fmaxf(y0, 0.0f), av);
                y1 = fminf(fmaxf(y1, 0.0f), av);
                float q0 = rintf(__fdiv_rn(__fmul_rn(y0, 15.0f), av));
                float q1 = rintf(__fdiv_rn(__fmul_rn(y1, 15.0f), av));
                *(float2*)(ob + nt * 8 + 2 * (l & 3)) =
                    make_float2(__fmul_rn(q0, aon), __fmul_rn(q1, aon));
            }
        }
    }
}

// ---------------------------------------------------------------------------
extern "C" void kernel_launch(void* const* d_in, const int* in_sizes, int n_in,
                              void* d_out, int out_size) {
    const float* x      = (const float*)d_in[0];
    const float* weight = (const float*)d_in[1];
    const float* gamma  = (const float*)d_in[2];
    const float* beta   = (const float*)d_in[3];
    const float* rmean  = (const float*)d_in[4];
    const float* rvar   = (const float*)d_in[5];
    const float* alpha  = (const float*)d_in[6];
    float* out = (float*)d_out;

    const int WELEMS = C_OUT * KD;

    cudaFuncSetAttribute(k_conv, cudaFuncAttributeMaxDynamicSharedMemorySize, SMEMT);

    k_reset<<<1, 1>>>();
    k_maxabs<<<256, 256>>>(weight, WELEMS);
    k_pack<<<(WELEMS + 255) / 256, 256>>>(weight);
    k_chan<<<1, C_OUT>>>(gamma, beta, rmean, rvar);
    k_split<<<BATCH * 16 * 58, 128>>>(x);

    dim3 grid(BATCH * 14, 4);
    k_conv<<<grid, 256, SMEMT>>>(out, alpha);
    (void)in_sizes; (void)n_in; (void)out_size;
}